// round 6
// baseline (speedup 1.0000x reference)
#include <cuda_runtime.h>

// PSD: psd[b,f,c,e] = sum_t (mask/(sum_t mask + eps)) * X[c,t] * conj(X[e,t])
// B=8, F=257, C=8, T=3000.  Harness compares REAL PART only:
//   out_size == BF*64  -> float32 (B,F,C,C) real part   (observed path)
//   out_size == BF*128 -> interleaved complex64         (fallback)

#define NCH 8
#define TLEN 3000
#define T2 (TLEN / 2)
#define NPAIR 28
#define NT 128
#define EPSV 1e-15f

__device__ __forceinline__ int pair_idx(int a, int b) {  // a < b
    return a * 7 - (a * (a + 1)) / 2 + b - 1;
}

// ---------------- real-part-only kernel (hot path) ----------------
__global__ __launch_bounds__(NT, 6)
void psd_real_kernel(const float* __restrict__ Xr,
                     const float* __restrict__ Xi,
                     const float* __restrict__ Mk,
                     float* __restrict__ out)
{
    const int bf  = blockIdx.x;
    const int tid = threadIdx.x;

    const float2* __restrict__ xr2 = (const float2*)(Xr + (size_t)bf * NCH * TLEN);
    const float2* __restrict__ xi2 = (const float2*)(Xi + (size_t)bf * NCH * TLEN);
    const float2* __restrict__ mk2 = (const float2*)(Mk + (size_t)bf * TLEN);

    __shared__ float red[NT / 32];
    __shared__ float s_inv;

    // mask sum over t (normalization folded into epilogue)
    float ms = 0.0f;
    for (int i = tid; i < T2; i += NT) { float2 m = mk2[i]; ms += m.x + m.y; }
    #pragma unroll
    for (int o = 16; o; o >>= 1) ms += __shfl_xor_sync(0xffffffffu, ms, o);
    if ((tid & 31) == 0) red[tid >> 5] = ms;
    __syncthreads();
    if (tid == 0) {
        float s = 0.0f;
        #pragma unroll
        for (int w = 0; w < NT / 32; w++) s += red[w];
        s_inv = 1.0f / (s + EPSV);
    }
    __syncthreads();
    const float inv = s_inv;

    // 36 accumulators: 8 diagonal + 28 upper-triangle real parts
    float acc[36];
    #pragma unroll
    for (int k = 0; k < 36; k++) acc[k] = 0.0f;

    for (int i = tid; i < T2; i += NT) {
        float2 m2 = mk2[i];
        float2 rv[NCH], iv[NCH];
        #pragma unroll
        for (int c = 0; c < NCH; c++) {
            rv[c] = xr2[c * T2 + i];
            iv[c] = xi2[c * T2 + i];
        }
        #pragma unroll
        for (int u = 0; u < 2; u++) {
            const float m = u ? m2.y : m2.x;
            // diagonal: acc += m * (xr^2 + xi^2)
            #pragma unroll
            for (int c = 0; c < NCH; c++) {
                float xr = u ? rv[c].y : rv[c].x;
                float xi = u ? iv[c].y : iv[c].x;
                float s  = xr * xr + xi * xi;
                acc[c] = fmaf(m, s, acc[c]);
            }
            // pairs: acc += m * (xr_c*xr_e + xi_c*xi_e)
            int p = 0;
            #pragma unroll
            for (int c = 0; c < NCH; c++) {
                float xrc = u ? rv[c].y : rv[c].x;
                float xic = u ? iv[c].y : iv[c].x;
                #pragma unroll
                for (int e = c + 1; e < NCH; e++) {
                    float xre = u ? rv[e].y : rv[e].x;
                    float xie = u ? iv[e].y : iv[e].x;
                    float s   = xrc * xre + xic * xie;
                    acc[8 + p] = fmaf(m, s, acc[8 + p]);
                    p++;
                }
            }
        }
    }

    // block reduction
    __shared__ float sums[NT / 32][36];
    #pragma unroll
    for (int k = 0; k < 36; k++) {
        float x = acc[k];
        #pragma unroll
        for (int o = 16; o; o >>= 1) x += __shfl_xor_sync(0xffffffffu, x, o);
        if ((tid & 31) == 0) sums[tid >> 5][k] = x;
    }
    __syncthreads();

    if (tid < 36) {
        float s = 0.0f;
        #pragma unroll
        for (int w = 0; w < NT / 32; w++) s += sums[w][tid];
        sums[0][tid] = s * inv;
    }
    __syncthreads();

    if (tid < 64) {
        const int c = tid >> 3;
        const int e = tid & 7;
        float re = (c == e) ? sums[0][c]
                            : sums[0][8 + pair_idx(min(c, e), max(c, e))];
        out[(size_t)bf * 64 + tid] = re;
    }
}

// ---------------- full-complex fallback ----------------
__global__ __launch_bounds__(NT, 1)
void psd_cplx_kernel(const float* __restrict__ Xr,
                     const float* __restrict__ Xi,
                     const float* __restrict__ Mk,
                     float2* __restrict__ out)
{
    const int bf  = blockIdx.x;
    const int tid = threadIdx.x;

    const float2* __restrict__ xr2 = (const float2*)(Xr + (size_t)bf * NCH * TLEN);
    const float2* __restrict__ xi2 = (const float2*)(Xi + (size_t)bf * NCH * TLEN);
    const float2* __restrict__ mk2 = (const float2*)(Mk + (size_t)bf * TLEN);

    __shared__ float red[NT / 32];
    __shared__ float s_inv;

    float ms = 0.0f;
    for (int i = tid; i < T2; i += NT) { float2 m = mk2[i]; ms += m.x + m.y; }
    #pragma unroll
    for (int o = 16; o; o >>= 1) ms += __shfl_xor_sync(0xffffffffu, ms, o);
    if ((tid & 31) == 0) red[tid >> 5] = ms;
    __syncthreads();
    if (tid == 0) {
        float s = 0.0f;
        #pragma unroll
        for (int w = 0; w < NT / 32; w++) s += red[w];
        s_inv = 1.0f / (s + EPSV);
    }
    __syncthreads();
    const float inv = s_inv;

    float acc[64];
    #pragma unroll
    for (int k = 0; k < 64; k++) acc[k] = 0.0f;

    for (int i = tid; i < T2; i += NT) {
        float2 m2 = mk2[i];
        float2 rv[NCH], iv[NCH];
        #pragma unroll
        for (int c = 0; c < NCH; c++) {
            rv[c] = xr2[c * T2 + i];
            iv[c] = xi2[c * T2 + i];
        }
        #pragma unroll
        for (int u = 0; u < 2; u++) {
            const float m = u ? m2.y : m2.x;
            #pragma unroll
            for (int c = 0; c < NCH; c++) {
                float xr = u ? rv[c].y : rv[c].x;
                float xi = u ? iv[c].y : iv[c].x;
                acc[c] = fmaf(m, xr * xr + xi * xi, acc[c]);
            }
            int p = 0;
            #pragma unroll
            for (int c = 0; c < NCH; c++) {
                float xrc = u ? rv[c].y : rv[c].x;
                float xic = u ? iv[c].y : iv[c].x;
                #pragma unroll
                for (int e = c + 1; e < NCH; e++) {
                    float xre = u ? rv[e].y : rv[e].x;
                    float xie = u ? iv[e].y : iv[e].x;
                    acc[8 + p]  = fmaf(m, xrc * xre + xic * xie, acc[8 + p]);
                    acc[36 + p] = fmaf(m, xic * xre - xrc * xie, acc[36 + p]);
                    p++;
                }
            }
        }
    }

    __shared__ float sums[NT / 32][64];
    #pragma unroll
    for (int k = 0; k < 64; k++) {
        float x = acc[k];
        #pragma unroll
        for (int o = 16; o; o >>= 1) x += __shfl_xor_sync(0xffffffffu, x, o);
        if ((tid & 31) == 0) sums[tid >> 5][k] = x;
    }
    __syncthreads();

    if (tid < 64) {
        float s = 0.0f;
        #pragma unroll
        for (int w = 0; w < NT / 32; w++) s += sums[w][tid];
        sums[0][tid] = s * inv;
    }
    __syncthreads();

    if (tid < 64) {
        const int c = tid >> 3;
        const int e = tid & 7;
        float re, imv;
        if (c == e)      { re = sums[0][c];                  imv = 0.0f; }
        else if (c < e)  { re = sums[0][8 + pair_idx(c, e)]; imv =  sums[0][36 + pair_idx(c, e)]; }
        else             { re = sums[0][8 + pair_idx(e, c)]; imv = -sums[0][36 + pair_idx(e, c)]; }
        out[(size_t)bf * 64 + tid] = make_float2(re, imv);
    }
}

extern "C" void kernel_launch(void* const* d_in, const int* in_sizes, int n_in,
                              void* d_out, int out_size)
{
    // Structural input identification: mask is the input 8x smaller than the X planes.
    int mask_idx = -1;
    for (int i = 0; i < 3; i++) {
        int bigger = 0;
        for (int j = 0; j < 3; j++)
            if (j != i && in_sizes[j] == in_sizes[i] * NCH) bigger++;
        if (bigger == 2) { mask_idx = i; break; }
    }
    if (mask_idx < 0) mask_idx = 2;

    int xa = -1, xb = -1;
    for (int i = 0; i < 3; i++) {
        if (i == mask_idx) continue;
        if (xa < 0) xa = i; else xb = i;
    }

    const float* Xr = (const float*)d_in[xa];
    const float* Xi = (const float*)d_in[xb];
    const float* Mk = (const float*)d_in[mask_idx];

    const int BF = in_sizes[mask_idx] / TLEN;   // B*F = 2056
    if (BF <= 0) return;

    if (out_size == BF * 64) {
        psd_real_kernel<<<BF, NT>>>(Xr, Xi, Mk, (float*)d_out);
    } else {
        psd_cplx_kernel<<<BF, NT>>>(Xr, Xi, Mk, (float2*)d_out);
    }
}

// round 7
// speedup vs baseline: 1.1943x; 1.1943x over previous
#include <cuda_runtime.h>

// PSD: psd[b,f,c,e] = sum_t (mask/(sum_t mask + eps)) * X[c,t] * conj(X[e,t])
// B=8, F=257, C=8, T=3000.  Harness compares REAL PART only:
//   out_size == BF*64  -> float32 (B,F,C,C) real part   (observed path)
//   out_size == BF*128 -> interleaved complex64         (fallback)

#define NCH 8
#define TLEN 3000
#define T2 (TLEN / 2)
#define NPAIR 28
#define NT 128
#define EPSV 1e-15f

__device__ __forceinline__ int pair_idx(int a, int b) {  // a < b
    return a * 7 - (a * (a + 1)) / 2 + b - 1;
}

// ---------------- real-part-only kernel (hot path) ----------------
// Natural reg footprint is 96 (measured R5). 5 CTAs * 128 thr * 96 regs = 61440
// fits the 64K RF; cap at 102 regs keeps codegen spill-free while raising
// residency 4 -> 5 CTAs/SM.
__global__ __launch_bounds__(NT, 5)
void psd_real_kernel(const float* __restrict__ Xr,
                     const float* __restrict__ Xi,
                     const float* __restrict__ Mk,
                     float* __restrict__ out)
{
    const int bf  = blockIdx.x;
    const int tid = threadIdx.x;

    const float2* __restrict__ xr2 = (const float2*)(Xr + (size_t)bf * NCH * TLEN);
    const float2* __restrict__ xi2 = (const float2*)(Xi + (size_t)bf * NCH * TLEN);
    const float2* __restrict__ mk2 = (const float2*)(Mk + (size_t)bf * TLEN);

    __shared__ float red[NT / 32];
    __shared__ float s_inv;

    // mask sum over t (normalization folded into epilogue)
    float ms = 0.0f;
    for (int i = tid; i < T2; i += NT) { float2 m = mk2[i]; ms += m.x + m.y; }
    #pragma unroll
    for (int o = 16; o; o >>= 1) ms += __shfl_xor_sync(0xffffffffu, ms, o);
    if ((tid & 31) == 0) red[tid >> 5] = ms;
    __syncthreads();
    if (tid == 0) {
        float s = 0.0f;
        #pragma unroll
        for (int w = 0; w < NT / 32; w++) s += red[w];
        s_inv = 1.0f / (s + EPSV);
    }
    __syncthreads();
    const float inv = s_inv;

    // 36 accumulators: 8 diagonal + 28 upper-triangle real parts
    float acc[36];
    #pragma unroll
    for (int k = 0; k < 36; k++) acc[k] = 0.0f;

    for (int i = tid; i < T2; i += NT) {
        float2 m2 = mk2[i];
        float2 rv[NCH], iv[NCH];
        #pragma unroll
        for (int c = 0; c < NCH; c++) {
            rv[c] = xr2[c * T2 + i];
            iv[c] = xi2[c * T2 + i];
        }
        #pragma unroll
        for (int u = 0; u < 2; u++) {
            const float m = u ? m2.y : m2.x;
            // diagonal: acc += m * (xr^2 + xi^2)
            #pragma unroll
            for (int c = 0; c < NCH; c++) {
                float xr = u ? rv[c].y : rv[c].x;
                float xi = u ? iv[c].y : iv[c].x;
                float s  = xr * xr + xi * xi;
                acc[c] = fmaf(m, s, acc[c]);
            }
            // pairs: acc += m * (xr_c*xr_e + xi_c*xi_e)
            int p = 0;
            #pragma unroll
            for (int c = 0; c < NCH; c++) {
                float xrc = u ? rv[c].y : rv[c].x;
                float xic = u ? iv[c].y : iv[c].x;
                #pragma unroll
                for (int e = c + 1; e < NCH; e++) {
                    float xre = u ? rv[e].y : rv[e].x;
                    float xie = u ? iv[e].y : iv[e].x;
                    float s   = xrc * xre + xic * xie;
                    acc[8 + p] = fmaf(m, s, acc[8 + p]);
                    p++;
                }
            }
        }
    }

    // block reduction
    __shared__ float sums[NT / 32][36];
    #pragma unroll
    for (int k = 0; k < 36; k++) {
        float x = acc[k];
        #pragma unroll
        for (int o = 16; o; o >>= 1) x += __shfl_xor_sync(0xffffffffu, x, o);
        if ((tid & 31) == 0) sums[tid >> 5][k] = x;
    }
    __syncthreads();

    if (tid < 36) {
        float s = 0.0f;
        #pragma unroll
        for (int w = 0; w < NT / 32; w++) s += sums[w][tid];
        sums[0][tid] = s * inv;
    }
    __syncthreads();

    if (tid < 64) {
        const int c = tid >> 3;
        const int e = tid & 7;
        float re = (c == e) ? sums[0][c]
                            : sums[0][8 + pair_idx(min(c, e), max(c, e))];
        out[(size_t)bf * 64 + tid] = re;
    }
}

// ---------------- full-complex fallback ----------------
__global__ __launch_bounds__(NT, 1)
void psd_cplx_kernel(const float* __restrict__ Xr,
                     const float* __restrict__ Xi,
                     const float* __restrict__ Mk,
                     float2* __restrict__ out)
{
    const int bf  = blockIdx.x;
    const int tid = threadIdx.x;

    const float2* __restrict__ xr2 = (const float2*)(Xr + (size_t)bf * NCH * TLEN);
    const float2* __restrict__ xi2 = (const float2*)(Xi + (size_t)bf * NCH * TLEN);
    const float2* __restrict__ mk2 = (const float2*)(Mk + (size_t)bf * TLEN);

    __shared__ float red[NT / 32];
    __shared__ float s_inv;

    float ms = 0.0f;
    for (int i = tid; i < T2; i += NT) { float2 m = mk2[i]; ms += m.x + m.y; }
    #pragma unroll
    for (int o = 16; o; o >>= 1) ms += __shfl_xor_sync(0xffffffffu, ms, o);
    if ((tid & 31) == 0) red[tid >> 5] = ms;
    __syncthreads();
    if (tid == 0) {
        float s = 0.0f;
        #pragma unroll
        for (int w = 0; w < NT / 32; w++) s += red[w];
        s_inv = 1.0f / (s + EPSV);
    }
    __syncthreads();
    const float inv = s_inv;

    float acc[64];
    #pragma unroll
    for (int k = 0; k < 64; k++) acc[k] = 0.0f;

    for (int i = tid; i < T2; i += NT) {
        float2 m2 = mk2[i];
        float2 rv[NCH], iv[NCH];
        #pragma unroll
        for (int c = 0; c < NCH; c++) {
            rv[c] = xr2[c * T2 + i];
            iv[c] = xi2[c * T2 + i];
        }
        #pragma unroll
        for (int u = 0; u < 2; u++) {
            const float m = u ? m2.y : m2.x;
            #pragma unroll
            for (int c = 0; c < NCH; c++) {
                float xr = u ? rv[c].y : rv[c].x;
                float xi = u ? iv[c].y : iv[c].x;
                acc[c] = fmaf(m, xr * xr + xi * xi, acc[c]);
            }
            int p = 0;
            #pragma unroll
            for (int c = 0; c < NCH; c++) {
                float xrc = u ? rv[c].y : rv[c].x;
                float xic = u ? iv[c].y : iv[c].x;
                #pragma unroll
                for (int e = c + 1; e < NCH; e++) {
                    float xre = u ? rv[e].y : rv[e].x;
                    float xie = u ? iv[e].y : iv[e].x;
                    acc[8 + p]  = fmaf(m, xrc * xre + xic * xie, acc[8 + p]);
                    acc[36 + p] = fmaf(m, xic * xre - xrc * xie, acc[36 + p]);
                    p++;
                }
            }
        }
    }

    __shared__ float sums[NT / 32][64];
    #pragma unroll
    for (int k = 0; k < 64; k++) {
        float x = acc[k];
        #pragma unroll
        for (int o = 16; o; o >>= 1) x += __shfl_xor_sync(0xffffffffu, x, o);
        if ((tid & 31) == 0) sums[tid >> 5][k] = x;
    }
    __syncthreads();

    if (tid < 64) {
        float s = 0.0f;
        #pragma unroll
        for (int w = 0; w < NT / 32; w++) s += sums[w][tid];
        sums[0][tid] = s * inv;
    }
    __syncthreads();

    if (tid < 64) {
        const int c = tid >> 3;
        const int e = tid & 7;
        float re, imv;
        if (c == e)      { re = sums[0][c];                  imv = 0.0f; }
        else if (c < e)  { re = sums[0][8 + pair_idx(c, e)]; imv =  sums[0][36 + pair_idx(c, e)]; }
        else             { re = sums[0][8 + pair_idx(e, c)]; imv = -sums[0][36 + pair_idx(e, c)]; }
        out[(size_t)bf * 64 + tid] = make_float2(re, imv);
    }
}

extern "C" void kernel_launch(void* const* d_in, const int* in_sizes, int n_in,
                              void* d_out, int out_size)
{
    // Structural input identification: mask is the input 8x smaller than the X planes.
    int mask_idx = -1;
    for (int i = 0; i < 3; i++) {
        int bigger = 0;
        for (int j = 0; j < 3; j++)
            if (j != i && in_sizes[j] == in_sizes[i] * NCH) bigger++;
        if (bigger == 2) { mask_idx = i; break; }
    }
    if (mask_idx < 0) mask_idx = 2;

    int xa = -1, xb = -1;
    for (int i = 0; i < 3; i++) {
        if (i == mask_idx) continue;
        if (xa < 0) xa = i; else xb = i;
    }

    const float* Xr = (const float*)d_in[xa];
    const float* Xi = (const float*)d_in[xb];
    const float* Mk = (const float*)d_in[mask_idx];

    const int BF = in_sizes[mask_idx] / TLEN;   // B*F = 2056
    if (BF <= 0) return;

    if (out_size == BF * 64) {
        psd_real_kernel<<<BF, NT>>>(Xr, Xi, Mk, (float*)d_out);
    } else {
        psd_cplx_kernel<<<BF, NT>>>(Xr, Xi, Mk, (float2*)d_out);
    }
}